// round 5
// baseline (speedup 1.0000x reference)
#include <cuda_runtime.h>
#include <cuda_bf16.h>
#include <cstdint>

// out = P5(x) / Q4(x) elementwise over x[4, 4096, 2048], 8 groups of 256 along D.
// Scalar FFMA Horner, segment-split items (1 group per thread), ITEMS=8 float4
// per thread batched up front for MLP=8.
// (Resubmission of round-4 kernel: previous round died on broker infra, not code.)

#define THREADS 256
#define ITEMS   8

__device__ __forceinline__ float rational(float z,
    float a0, float a1, float a2, float a3, float a4, float a5,
    float c1, float c2, float c3, float c4)
{
    float num = fmaf(fmaf(fmaf(fmaf(fmaf(a5, z, a4), z, a3), z, a2), z, a1), z, a0);
    float den = fmaf(fmaf(fmaf(fmaf(c4, z, c3), z, c2), z, c1), z, 1.0f);
    return __fdividef(num, den);
}

// Fast path: n4 % (ITEMS*THREADS) == 0 and (n4/ITEMS) % 512 == 0, so each
// thread's ITEMS elements (strided by seg) all live in the same group.
__global__ __launch_bounds__(THREADS, 5)
void kat_rational_seg(const float4* __restrict__ x4,
                      const float*  __restrict__ wnum,
                      const float*  __restrict__ wden,
                      float4* __restrict__ out4,
                      int seg)                 // float4s per segment
{
    int t = blockIdx.x * THREADS + threadIdx.x;

    // ---- Batch all stream loads first (MLP = ITEMS) ----
    float4 v[ITEMS];
    #pragma unroll
    for (int j = 0; j < ITEMS; ++j)
        v[j] = __ldcs(&x4[t + j * seg]);

    // ---- Coefficients: 3 warp-uniform vector loads ----
    float4 a03 = __ldg((const float4*)wnum);
    float  a4  = __ldg(wnum + 4);
    float  a5  = __ldg(wnum + 5);
    int g = (t >> 6) & 7;                       // 64 float4 per group chunk
    float4 bb = __ldg((const float4*)(wden + g * 4));
    float c1 = fabsf(bb.x), c2 = fabsf(bb.y), c3 = fabsf(bb.z), c4 = fabsf(bb.w);

    // ---- Compute + store ----
    #pragma unroll
    for (int j = 0; j < ITEMS; ++j) {
        float4 r;
        r.x = rational(v[j].x, a03.x,a03.y,a03.z,a03.w,a4,a5, c1,c2,c3,c4);
        r.y = rational(v[j].y, a03.x,a03.y,a03.z,a03.w,a4,a5, c1,c2,c3,c4);
        r.z = rational(v[j].z, a03.x,a03.y,a03.z,a03.w,a4,a5, c1,c2,c3,c4);
        r.w = rational(v[j].w, a03.x,a03.y,a03.z,a03.w,a4,a5, c1,c2,c3,c4);
        __stcs(&out4[t + j * seg], r);
    }
}

// Generic fallback (any size), scalar path.
__global__ __launch_bounds__(THREADS)
void kat_rational_generic(const float* __restrict__ x,
                          const float* __restrict__ wnum,
                          const float* __restrict__ wden,
                          float* __restrict__ out,
                          int n)
{
    int i = blockIdx.x * THREADS + threadIdx.x;
    if (i >= n) return;
    int g = (i % 2048) / 256;
    float a0 = wnum[0], a1 = wnum[1], a2 = wnum[2], a3 = wnum[3], a4 = wnum[4], a5 = wnum[5];
    float c1 = fabsf(wden[g*4+0]), c2 = fabsf(wden[g*4+1]);
    float c3 = fabsf(wden[g*4+2]), c4 = fabsf(wden[g*4+3]);
    float z = x[i];
    float num = fmaf(fmaf(fmaf(fmaf(fmaf(a5, z, a4), z, a3), z, a2), z, a1), z, a0);
    float den = fmaf(fmaf(fmaf(fmaf(c4, z, c3), z, c2), z, c1), z, 1.0f);
    out[i] = __fdividef(num, den);
}

extern "C" void kernel_launch(void* const* d_in, const int* in_sizes, int n_in,
                              void* d_out, int out_size)
{
    const float* x    = (const float*)d_in[0];
    const float* wnum = (const float*)d_in[1];
    const float* wden = (const float*)d_in[2];
    float* out        = (float*)d_out;

    int n  = in_sizes[0];     // 33,554,432
    int n4 = n >> 2;          // 8,388,608 float4s
    int seg = n4 / ITEMS;     // 1,048,576 float4s per segment

    bool fast = (n % 4 == 0) && (n4 % (ITEMS * THREADS) == 0) && (seg % 512 == 0);
    if (fast) {
        int blocks = seg / THREADS;   // 4096
        kat_rational_seg<<<blocks, THREADS>>>((const float4*)x, wnum, wden,
                                              (float4*)out, seg);
    } else {
        int blocks = (n + THREADS - 1) / THREADS;
        kat_rational_generic<<<blocks, THREADS>>>(x, wnum, wden, out, n);
    }
}